// round 7
// baseline (speedup 1.0000x reference)
#include <cuda_runtime.h>
#include <cuda_fp16.h>
#include <cstdint>

// Flow_68015102099543: implicit-GEMM conv3x3 via warp mma (fp16 in, fp32 accum).
// out[b,o,h,w] = bias[o] + sum_{i,c} comb[o, i*16+c] * x[b,c,h+dy_i,w+dx_i]
// B=4, C=16, O=16, H=450, W=480.
// Warp tile = 2 rows x 32 px (32 accumulator regs) -> ~64 regs/thread -> 4 CTAs/SM
// (50% occ) while keeping R6's dy-reuse of B fragments (192 B/px LDS).

#define HH 450
#define WW 480

#define CTA_H 8         // output rows per CTA (4 row-pairs)
#define CTA_W 64        // output cols per CTA (2 col-halves of 32)
#define HSX 10          // staged rows  (CTA_H + 2)
#define WSX 66          // staged w pos (CTA_W + 2)

__device__ __forceinline__ uint32_t smem_u32(const void* p) {
    return (uint32_t)__cvta_generic_to_shared(p);
}

__device__ __forceinline__ void ldsm_x4(uint32_t& r0, uint32_t& r1, uint32_t& r2, uint32_t& r3,
                                        uint32_t a) {
    asm volatile("ldmatrix.sync.aligned.m8n8.x4.shared.b16 {%0,%1,%2,%3}, [%4];"
                 : "=r"(r0), "=r"(r1), "=r"(r2), "=r"(r3) : "r"(a));
}
__device__ __forceinline__ void ldsm_x2(uint32_t& r0, uint32_t& r1, uint32_t a) {
    asm volatile("ldmatrix.sync.aligned.m8n8.x2.shared.b16 {%0,%1}, [%2];"
                 : "=r"(r0), "=r"(r1) : "r"(a));
}

__device__ __forceinline__ void mma_fp16(float* d, const uint32_t* a,
                                         uint32_t b0, uint32_t b1) {
    asm volatile("mma.sync.aligned.m16n8k16.row.col.f32.f16.f16.f32 "
                 "{%0,%1,%2,%3}, {%4,%5,%6,%7}, {%8,%9}, {%0,%1,%2,%3};"
                 : "+f"(d[0]), "+f"(d[1]), "+f"(d[2]), "+f"(d[3])
                 : "r"(a[0]), "r"(a[1]), "r"(a[2]), "r"(a[3]), "r"(b0), "r"(b1));
}

__global__ void __launch_bounds__(256, 4) flow_mma4_kernel(
    const float* __restrict__ x,      // [4,16,450,480]
    const float* __restrict__ comb,   // [16,144]
    const float* __restrict__ bias,   // [16]
    float* __restrict__ out)          // [4,16,450,480]
{
    // x tile: [h_s][w_s][half] 16B units (8 fp16 ch), half swizzled by (w_s>>2)&1
    __shared__ uint4 xs4[HSX * WSX * 2];      // 21120 B
    // weights: [flow][o][half] 16B units, half swizzled by (o>>2)&1
    __shared__ uint4 ws4[9 * 16 * 2];         // 4608 B

    const int tid = threadIdx.x;
    const int b  = blockIdx.z;
    const int h0 = blockIdx.y * CTA_H;
    const int w0 = (blockIdx.x * CTA_W < WW - CTA_W) ? blockIdx.x * CTA_W : (WW - CTA_W);

    // ---- stage weights (fp32 -> fp16) ----
    for (int idx = tid; idx < 9 * 16 * 16; idx += 256) {
        int i = idx >> 8, o = (idx >> 4) & 15, c = idx & 15;
        float v = comb[o * 144 + i * 16 + c];
        int half_ = c >> 3;
        int phys = (i * 16 + o) * 2 + (half_ ^ ((o >> 2) & 1));
        ((__half*)ws4)[phys * 8 + (c & 7)] = __float2half(v);
    }

    // ---- stage x tile: rows h0-1..h0+8, cols w0-1..w0+64, zero-padded ----
    for (int u = tid; u < HSX * 2 * WSX; u += 256) {
        int w_s   = u % WSX;
        int t     = u / WSX;
        int half_ = t & 1;
        int h_s   = t >> 1;
        int gh = h0 - 1 + h_s;
        int gw = w0 - 1 + w_s;
        bool ok = ((unsigned)gh < (unsigned)HH) && ((unsigned)gw < (unsigned)WW);
        const float* xp = x + (((size_t)(b * 16 + half_ * 8) * HH + gh) * WW + gw);
        float v[8];
#pragma unroll
        for (int cc = 0; cc < 8; cc++)
            v[cc] = ok ? __ldg(xp + (size_t)cc * (HH * WW)) : 0.0f;
        uint32_t pk[4];
#pragma unroll
        for (int cc = 0; cc < 4; cc++) {
            __half2 p = __floats2half2_rn(v[2 * cc], v[2 * cc + 1]);
            pk[cc] = *(uint32_t*)&p;
        }
        xs4[(h_s * WSX + w_s) * 2 + (half_ ^ ((w_s >> 2) & 1))] =
            make_uint4(pk[0], pk[1], pk[2], pk[3]);
    }
    __syncthreads();

    const int wid  = tid >> 5;
    const int lane = tid & 31;
    const int ww_  = wid & 1;      // col half (32 px)
    const int wh   = wid >> 1;     // row pair (rows h0 + wh*2 + {0,1})

    // accumulators: acc[r][g][0..3]; (o = lane>>2, o+8) x (pix = (lane&3)*2 + {0,1})
    const int og = lane >> 2;
    const float b0v = __ldg(bias + og);
    const float b8v = __ldg(bias + 8 + og);
    float acc[2][4][4];
#pragma unroll
    for (int r = 0; r < 2; r++)
#pragma unroll
        for (int g = 0; g < 4; g++) {
            acc[r][g][0] = b0v; acc[r][g][1] = b0v;
            acc[r][g][2] = b8v; acc[r][g][3] = b8v;
        }

    const uint32_t wbase = smem_u32(ws4);
    const uint32_t xbase = smem_u32(xs4) + (uint32_t)(wh * 2) * (WSX * 32);

    // A-frag lane addressing (proven scheme)
    const int o_l   = ((lane >> 3) & 1) * 8 + (lane & 7);
    const int ahalf = (lane >> 4) & 1;
    const uint32_t aoff = (uint32_t)((o_l * 2 + (ahalf ^ ((o_l >> 2) & 1))) * 16);
    // B-frag lane addressing
    const int bp    = lane & 7;
    const int bhalf = (lane >> 3) & 1;

#pragma unroll
    for (int dx = 0; dx < 3; dx++) {
        uint32_t a[3][4];   // weight frags for dy = 0,1,2 at this dx
#pragma unroll
        for (int dy = 0; dy < 3; dy++)
            ldsm_x4(a[dy][0], a[dy][1], a[dy][2], a[dy][3],
                    wbase + (uint32_t)(dy * 3 + dx) * 512u + aoff);
#pragma unroll
        for (int g = 0; g < 4; g++) {
            const int w_s = ww_ * 32 + g * 8 + dx + bp;
            const uint32_t bo_col = (uint32_t)((w_s * 2 + (bhalf ^ ((w_s >> 2) & 1))) * 16);
            // staged rows ii = 0..3 relative to warp base (wh*2)
#pragma unroll
            for (int ii = 0; ii < 4; ii++) {
                uint32_t b0f, b1f;
                ldsm_x2(b0f, b1f, xbase + (uint32_t)(ii * WSX * 32) + bo_col);
                // input row ii serves output rows r = ii - dy, r in {0,1}
#pragma unroll
                for (int dy = 0; dy < 3; dy++) {
                    const int r = ii - dy;
                    if (r >= 0 && r < 2)
                        mma_fp16(acc[r][g], a[dy], b0f, b1f);
                }
            }
        }
    }

    // ---- store: 2 consecutive pixels per STG.64 on o and o+8 planes ----
    const int pw = (lane & 3) * 2;
#pragma unroll
    for (int r = 0; r < 2; r++) {
        const int h = h0 + wh * 2 + r;
        if (h < HH) {
            float* op0 = out + ((((size_t)b * 16 + og) * HH + h) * WW + w0 + ww_ * 32 + pw);
            float* op8 = op0 + (size_t)8 * HH * WW;
#pragma unroll
            for (int g = 0; g < 4; g++) {
                float2 v01; v01.x = acc[r][g][0]; v01.y = acc[r][g][1];
                float2 v23; v23.x = acc[r][g][2]; v23.y = acc[r][g][3];
                *(float2*)(op0 + g * 8) = v01;
                *(float2*)(op8 + g * 8) = v23;
            }
        }
    }
}

extern "C" void kernel_launch(void* const* d_in, const int* in_sizes, int n_in,
                              void* d_out, int out_size) {
    const float* x    = (const float*)d_in[0];
    const float* comb = (const float*)d_in[1];
    const float* bias = (const float*)d_in[2];
    float* out = (float*)d_out;

    dim3 grid((WW + CTA_W - 1) / CTA_W, (HH + CTA_H - 1) / CTA_H, 4);  // (8, 57, 4) = 1824
    flow_mma4_kernel<<<grid, 256>>>(x, comb, bias, out);
}

// round 8
// speedup vs baseline: 1.0506x; 1.0506x over previous
#include <cuda_runtime.h>
#include <cuda_fp16.h>
#include <cstdint>

// Flow_68015102099543: implicit-GEMM conv3x3 via warp mma (fp16 in, fp32 accum),
// batch-pipelined: each CTA owns one (h,w) tile and iterates b=0..3 with
// double-buffered smem staging overlapped with compute. 570 CTAs = ONE wave.

#define HH 450
#define WW 480
#define HW (HH * WW)

#define CTA_H 8
#define CTA_W 48
#define HSX 10          // staged rows  (CTA_H + 2)
#define WSX 50          // staged w pos (CTA_W + 2)
#define NPOS (HSX * WSX * 2)   // 1000 uint4 slots per buffer

__device__ __forceinline__ uint32_t smem_u32(const void* p) {
    return (uint32_t)__cvta_generic_to_shared(p);
}

__device__ __forceinline__ void ldsm_x4(uint32_t& r0, uint32_t& r1, uint32_t& r2, uint32_t& r3,
                                        uint32_t a) {
    asm volatile("ldmatrix.sync.aligned.m8n8.x4.shared.b16 {%0,%1,%2,%3}, [%4];"
                 : "=r"(r0), "=r"(r1), "=r"(r2), "=r"(r3) : "r"(a));
}
__device__ __forceinline__ void ldsm_x2(uint32_t& r0, uint32_t& r1, uint32_t a) {
    asm volatile("ldmatrix.sync.aligned.m8n8.x2.shared.b16 {%0,%1}, [%2];"
                 : "=r"(r0), "=r"(r1) : "r"(a));
}

__device__ __forceinline__ void mma_fp16(float* d, const uint32_t* a,
                                         uint32_t b0, uint32_t b1) {
    asm volatile("mma.sync.aligned.m16n8k16.row.col.f32.f16.f16.f32 "
                 "{%0,%1,%2,%3}, {%4,%5,%6,%7}, {%8,%9}, {%0,%1,%2,%3};"
                 : "+f"(d[0]), "+f"(d[1]), "+f"(d[2]), "+f"(d[3])
                 : "r"(a[0]), "r"(a[1]), "r"(a[2]), "r"(a[3]), "r"(b0), "r"(b1));
}

// Load one staging position (8 channel floats) for batch `bb` into v[8].
__device__ __forceinline__ void ldg_chunk(float* v, const float* __restrict__ x,
                                          int bb, int h0, int w0, int u) {
    if (u >= NPOS) return;
    int h_s = u / 100;
    int rem = u - h_s * 100;
    int w_s = rem >> 1;
    int half_ = rem & 1;
    int gh = h0 - 1 + h_s;
    int gw = w0 - 1 + w_s;
    bool ok = ((unsigned)gh < (unsigned)HH) && ((unsigned)gw < (unsigned)WW);
    const float* p = x + ((size_t)(bb * 16 + half_ * 8) * HW) + gh * WW + gw;
#pragma unroll
    for (int cc = 0; cc < 8; cc++)
        v[cc] = ok ? __ldg(p + (size_t)cc * HW) : 0.0f;
}

// Convert + store one staging position into buffer `buf`.
__device__ __forceinline__ void sts_chunk(uint4* buf, const float* v, int u) {
    if (u >= NPOS) return;
    int h_s = u / 100;
    int rem = u - h_s * 100;
    int w_s = rem >> 1;
    int half_ = rem & 1;
    uint32_t pk[4];
#pragma unroll
    for (int cc = 0; cc < 4; cc++) {
        __half2 p = __floats2half2_rn(v[2 * cc], v[2 * cc + 1]);
        pk[cc] = *(uint32_t*)&p;
    }
    buf[(h_s * WSX + w_s) * 2 + (half_ ^ ((w_s >> 2) & 1))] =
        make_uint4(pk[0], pk[1], pk[2], pk[3]);
}

__global__ void __launch_bounds__(256, 4) flow_pipe_kernel(
    const float* __restrict__ x,      // [4,16,450,480]
    const float* __restrict__ comb,   // [16,144]
    const float* __restrict__ bias,   // [16]
    float* __restrict__ out)          // [4,16,450,480]
{
    __shared__ uint4 xs4[2][NPOS];    // 2 x 16000 B
    __shared__ uint4 ws4[9 * 16 * 2]; // 4608 B

    const int tid = threadIdx.x;
    const int h0 = blockIdx.y * CTA_H;
    const int w0 = blockIdx.x * CTA_W;

    // ---- stage weights once (fp32 -> fp16) ----
    for (int idx = tid; idx < 9 * 16 * 16; idx += 256) {
        int i = idx >> 8, o = (idx >> 4) & 15, c = idx & 15;
        float v = comb[o * 144 + i * 16 + c];
        int half_ = c >> 3;
        int phys = (i * 16 + o) * 2 + (half_ ^ ((o >> 2) & 1));
        ((__half*)ws4)[phys * 8 + (c & 7)] = __float2half(v);
    }

    // ---- stage batch 0 into buffer 0 ----
    {
        float v[8];
#pragma unroll
        for (int k = 0; k < 4; k++) {
            int u = k * 256 + tid;
            ldg_chunk(v, x, 0, h0, w0, u);
            sts_chunk(xs4[0], v, u);
        }
    }
    __syncthreads();

    const int wid  = tid >> 5;
    const int lane = tid & 31;
    const int ww_  = wid & 1;      // col half (24 px)
    const int wh   = wid >> 1;     // row pair (rows h0 + wh*2 + {0,1})

    const int og = lane >> 2;
    const float b0v = __ldg(bias + og);
    const float b8v = __ldg(bias + 8 + og);

    const uint32_t wbase = smem_u32(ws4);
    // A-frag lane addressing (proven scheme)
    const int o_l   = ((lane >> 3) & 1) * 8 + (lane & 7);
    const int ahalf = (lane >> 4) & 1;
    const uint32_t aoff = (uint32_t)((o_l * 2 + (ahalf ^ ((o_l >> 2) & 1))) * 16);
    const int bp = lane & 7;

#pragma unroll
    for (int bb = 0; bb < 4; bb++) {
        const int cur = bb & 1;
        uint4* nbuf = xs4[1 - cur];

        float v0[8], v1[8];
        if (bb < 3) {
            ldg_chunk(v0, x, bb + 1, h0, w0, tid);          // chunk 0
            ldg_chunk(v1, x, bb + 1, h0, w0, 256 + tid);    // chunk 1
        }

        // accumulators: acc[r][g][0..3]
        float acc[2][3][4];
#pragma unroll
        for (int r = 0; r < 2; r++)
#pragma unroll
            for (int g = 0; g < 3; g++) {
                acc[r][g][0] = b0v; acc[r][g][1] = b0v;
                acc[r][g][2] = b8v; acc[r][g][3] = b8v;
            }

        const uint32_t xb = smem_u32(xs4[cur]) + (uint32_t)(wh * 2) * (WSX * 32);

#pragma unroll
        for (int dx = 0; dx < 3; dx++) {
            uint32_t a[3][4];
#pragma unroll
            for (int dy = 0; dy < 3; dy++)
                ldsm_x4(a[dy][0], a[dy][1], a[dy][2], a[dy][3],
                        wbase + (uint32_t)(dy * 3 + dx) * 512u + aoff);

            // lane-resident column offsets (independent of ii)
            const int w_sA = ww_ * 24 + ((lane >> 4) & 1) * 8 + dx + bp;   // groups 0,1
            const uint32_t colA =
                (uint32_t)((w_sA * 2 + (((lane >> 3) & 1) ^ ((w_sA >> 2) & 1))) * 16);
            const int w_sC = ww_ * 24 + 16 + dx + bp;                       // group 2
            const uint32_t colC =
                (uint32_t)((w_sC * 2 + (((lane >> 3) & 1) ^ ((w_sC >> 2) & 1))) * 16);

#pragma unroll
            for (int ii = 0; ii < 4; ii++) {
                const uint32_t rowoff = (uint32_t)(ii * (WSX * 32));
                uint32_t q0, q1, q2, q3, s0, s1;
                ldsm_x4(q0, q1, q2, q3, xb + rowoff + colA);   // g0:(q0,q1) g1:(q2,q3)
                ldsm_x2(s0, s1, xb + rowoff + colC);           // g2:(s0,s1)
#pragma unroll
                for (int dy = 0; dy < 3; dy++) {
                    const int r = ii - dy;
                    if (r >= 0 && r < 2) {
                        mma_fp16(acc[r][0], a[dy], q0, q1);
                        mma_fp16(acc[r][1], a[dy], q2, q3);
                        mma_fp16(acc[r][2], a[dy], s0, s1);
                    }
                }
            }

            if (bb < 3) {
                if (dx == 0) { sts_chunk(nbuf, v0, tid);
                               ldg_chunk(v0, x, bb + 1, h0, w0, 512 + tid); }
                if (dx == 1) { sts_chunk(nbuf, v1, 256 + tid);
                               ldg_chunk(v1, x, bb + 1, h0, w0, 768 + tid); }
                if (dx == 2) { sts_chunk(nbuf, v0, 512 + tid); }
            }
        }

        // ---- epilogue store for batch bb ----
        const int pw = (lane & 3) * 2;
#pragma unroll
        for (int r = 0; r < 2; r++) {
            const int h = h0 + wh * 2 + r;
            if (h < HH) {
                float* op0 = out + ((((size_t)bb * 16 + og) * HH + h) * WW
                                    + w0 + ww_ * 24 + pw);
                float* op8 = op0 + (size_t)8 * HW;
#pragma unroll
                for (int g = 0; g < 3; g++) {
                    float2 u01; u01.x = acc[r][g][0]; u01.y = acc[r][g][1];
                    float2 u23; u23.x = acc[r][g][2]; u23.y = acc[r][g][3];
                    *(float2*)(op0 + g * 8) = u01;
                    *(float2*)(op8 + g * 8) = u23;
                }
            }
        }

        if (bb < 3) sts_chunk(nbuf, v1, 768 + tid);
        __syncthreads();
    }
}

extern "C" void kernel_launch(void* const* d_in, const int* in_sizes, int n_in,
                              void* d_out, int out_size) {
    const float* x    = (const float*)d_in[0];
    const float* comb = (const float*)d_in[1];
    const float* bias = (const float*)d_in[2];
    float* out = (float*)d_out;

    dim3 grid(WW / CTA_W, (HH + CTA_H - 1) / CTA_H, 1);   // (10, 57) = 570 CTAs, 1 wave
    flow_pipe_kernel<<<grid, 256>>>(x, comb, bias, out);
}